// round 10
// baseline (speedup 1.0000x reference)
#include <cuda_runtime.h>

#define FULL_MASK 0xFFFFFFFFu
static constexpr int HID = 32;
static constexpr int TT = 1024;
static constexpr int WARPS_PER_CTA = 4;

// ---- packed f32x2 helpers (sm_103a; ptxas never auto-fuses these) ----
__device__ __forceinline__ unsigned long long pack2(float lo, float hi) {
    unsigned long long r;
    asm("mov.b64 %0, {%1, %2};" : "=l"(r) : "f"(lo), "f"(hi));
    return r;
}
__device__ __forceinline__ void unpack2(unsigned long long v, float& lo, float& hi) {
    asm("mov.b64 {%0, %1}, %2;" : "=f"(lo), "=f"(hi) : "l"(v));
}
__device__ __forceinline__ unsigned long long fma2(unsigned long long a,
                                                   unsigned long long b,
                                                   unsigned long long c) {
    unsigned long long d;
    asm("fma.rn.f32x2 %0, %1, %2, %3;" : "=l"(d) : "l"(a), "l"(b), "l"(c));
    return d;
}
// single-MUFU tanh (MUFU.TANH, sm_75+; rel err ~2^-11 per call, measured
// 8.9e-7 end-to-end through this contractive recurrence)
__device__ __forceinline__ float tanh_approx(float x) {
    float r; asm("tanh.approx.f32 %0, %1;" : "=f"(r) : "f"(x)); return r;
}

// One warp per cell, lane j owns hidden unit j. k-packed weights (128 regs).
// sigmoid(x) = 0.5 + 0.5*tanh(x/2), /2 prescaled into i,f,o weight rows.
//
// ROUND-10 CHANGE: anti-lockstep skew. The 3 CTAs co-resident on an SM have
// distinct blockIdx.x % 3 (148 % 3 == 1), and warp k of each CTA lands on
// SMSP k. Identical code at identical rates phase-locks them, starving the
// SMSP during every step's low-issue head (sync+LDS) and tail (MUFU chain).
// A dead dependent-FMA preamble of ~0/140/280 cycles staggers them by ~1/3
// step period so each warp's fma-dense body covers the others' stalls.
__global__ void __launch_bounds__(WARPS_PER_CTA * 32, 3)
lstm_kernel(const float* __restrict__ x,
            const float* __restrict__ W_ih,
            const float* __restrict__ W_hh,
            const float* __restrict__ b_ih,
            const float* __restrict__ b_hh,
            const float* __restrict__ fc_W,
            const float* __restrict__ fc_b,
            float* __restrict__ out, int B)
{
    __shared__ __align__(16) float hbuf[WARPS_PER_CTA][2][HID];
    const int warp = threadIdx.x >> 5;
    const int lane = threadIdx.x & 31;
    const int b = blockIdx.x * WARPS_PER_CTA + warp;
    if (b >= B) return;   // warp-uniform

    // Gate order (PyTorch): rows [0:32)=i, [32:64)=f, [64:96)=g, [96:128)=o
    // Prescale i,f,o rows by 0.5 (sigmoid-via-tanh); g row unscaled.
    const float gscale[4] = { 0.5f, 0.5f, 1.0f, 0.5f };
    unsigned long long Wg[4][HID / 2];
    #pragma unroll
    for (int g = 0; g < 4; ++g) {
        const float* wrow = W_hh + (g * HID + lane) * HID;
        const float sc = gscale[g];
        #pragma unroll
        for (int k2 = 0; k2 < HID / 2; ++k2)
            Wg[g][k2] = pack2(sc * wrow[2 * k2], sc * wrow[2 * k2 + 1]);
    }
    const float wih_i = 0.5f * W_ih[0 * HID + lane];
    const float wih_f = 0.5f * W_ih[1 * HID + lane];
    const float wih_g =        W_ih[2 * HID + lane];
    const float wih_o = 0.5f * W_ih[3 * HID + lane];
    const float bias_i = 0.5f * (b_ih[0 * HID + lane] + b_hh[0 * HID + lane]);
    const float bias_f = 0.5f * (b_ih[1 * HID + lane] + b_hh[1 * HID + lane]);
    const float bias_g =        (b_ih[2 * HID + lane] + b_hh[2 * HID + lane]);
    const float bias_o = 0.5f * (b_ih[3 * HID + lane] + b_hh[3 * HID + lane]);

    // ---- anti-lockstep skew: dead dependent FMA chain, (bid%3)*35 FMAs ----
    {
        const int skew = (blockIdx.x % 3) * 35;   // ~0 / 140 / 280 cycles
        float d = 1.0f;
        for (int i = 0; i < skew; ++i)
            asm volatile("fma.rn.f32 %0, %0, 0f3F800000, 0f00000000;" : "+f"(d));
    }

    float h = 0.0f, c = 0.0f;
    const float* xrow = x + (size_t)b * TT;   // x is [B, T, 1]

    for (int t0 = 0; t0 < TT; t0 += 32) {
        // one coalesced 128B read per warp per 32 steps
        const float xbuf = xrow[t0 + lane];
        #pragma unroll 1
        for (int s = 0; s < 32; ++s) {
            const float xv = __shfl_sync(FULL_MASK, xbuf, s);

            float* buf = hbuf[warp][s & 1];
            buf[lane] = h;
            __syncwarp();

            // acc init = (prescaled gate base, 0)
            unsigned long long ai = pack2(fmaf(xv, wih_i, bias_i), 0.0f);
            unsigned long long af = pack2(fmaf(xv, wih_f, bias_f), 0.0f);
            unsigned long long ag = pack2(fmaf(xv, wih_g, bias_g), 0.0f);
            unsigned long long ao = pack2(fmaf(xv, wih_o, bias_o), 0.0f);

            const ulonglong2* hp = reinterpret_cast<const ulonglong2*>(buf);
            #pragma unroll
            for (int k4 = 0; k4 < HID / 4; ++k4) {
                const ulonglong2 hk = hp[k4];   // LDS.128 broadcast: 2 h-pairs
                ai = fma2(Wg[0][2 * k4], hk.x, ai);
                af = fma2(Wg[1][2 * k4], hk.x, af);
                ag = fma2(Wg[2][2 * k4], hk.x, ag);
                ao = fma2(Wg[3][2 * k4], hk.x, ao);
                ai = fma2(Wg[0][2 * k4 + 1], hk.y, ai);
                af = fma2(Wg[1][2 * k4 + 1], hk.y, af);
                ag = fma2(Wg[2][2 * k4 + 1], hk.y, ag);
                ao = fma2(Wg[3][2 * k4 + 1], hk.y, ao);
            }

            float lo, hi;
            unpack2(ai, lo, hi);  const float ti = tanh_approx(lo + hi);
            unpack2(af, lo, hi);  const float tf = tanh_approx(lo + hi);
            unpack2(ag, lo, hi);  const float gg = tanh_approx(lo + hi);
            unpack2(ao, lo, hi);  const float to = tanh_approx(lo + hi);

            const float ig = fmaf(0.5f, ti, 0.5f);
            const float fg = fmaf(0.5f, tf, 0.5f);
            const float og = fmaf(0.5f, to, 0.5f);

            c = fmaf(fg, c, ig * gg);
            h = og * tanh_approx(c);
        }
    }

    // out[b] = h . fc_W + fc_b  (warp reduce)
    float v = h * fc_W[lane];
    #pragma unroll
    for (int off = 16; off; off >>= 1)
        v += __shfl_xor_sync(FULL_MASK, v, off);
    if (lane == 0) out[b] = v + fc_b[0];
}

extern "C" void kernel_launch(void* const* d_in, const int* in_sizes, int n_in,
                              void* d_out, int out_size) {
    const float* x    = (const float*)d_in[0];
    const float* W_ih = (const float*)d_in[1];
    const float* W_hh = (const float*)d_in[2];
    const float* b_ih = (const float*)d_in[3];
    const float* b_hh = (const float*)d_in[4];
    const float* fc_W = (const float*)d_in[5];
    const float* fc_b = (const float*)d_in[6];
    float* out = (float*)d_out;

    const int B = in_sizes[0] / TT;           // x is B*T*1 elements
    const int ctas = (B + WARPS_PER_CTA - 1) / WARPS_PER_CTA;
    lstm_kernel<<<ctas, WARPS_PER_CTA * 32>>>(x, W_ih, W_hh, b_ih, b_hh,
                                              fc_W, fc_b, out, B);
}